// round 13
// baseline (speedup 1.0000x reference)
#include <cuda_runtime.h>
#include <cstdint>

#define NUM_HEADS 4
#define D 100
#define D4 25
#define NW 39
#define NT 160
#define G 4                 // groups per block
#define TILE_FLOATS 4000
#define TILE_VEC4 1000
#define C_ABS 0.5384615384615384f   // 0.35/0.65 : leaky(p) = 0.65*(p + C_ABS*|p|)
#define C_SCL 0.65f

__device__ __forceinline__ void cp_async16(uint32_t dst, const void* src) {
    asm volatile("cp.async.cg.shared.global [%0], [%1], 16;" :: "r"(dst), "l"(src));
}
__device__ __forceinline__ void cp_commit() {
    asm volatile("cp.async.commit_group;");
}

__global__ __launch_bounds__(NT, 4)
void tse_kernel(const float* __restrict__ x,
                const float* __restrict__ w_att,
                const float* __restrict__ b_att,
                float* __restrict__ out,
                int n_groups)
{
    __shared__ float  s_tile[2][TILE_FLOATS];   // 32.0 KB raw tiles (row w at w*100)
    __shared__ float4 s_part[NW * D4];          // 15.6 KB partial scores [n][j]->{h0..h3}
    __shared__ float4 s_e4[NW];
    __shared__ float  s_inv[NUM_HEADS];
    __shared__ int    s_nz;

    const int t  = threadIdx.x;
    const int g0 = blockIdx.x * G;

    // ---- params -> registers once per block (L2-hot) ----
    const int jp = t % D4;
    const int nr = t / D4;
    float4 wa0 = reinterpret_cast<const float4*>(w_att)[0 * D4 + jp];
    float4 wa1 = reinterpret_cast<const float4*>(w_att)[1 * D4 + jp];
    float4 wa2 = reinterpret_cast<const float4*>(w_att)[2 * D4 + jp];
    float4 wa3 = reinterpret_cast<const float4*>(w_att)[3 * D4 + jp];
    float4 ba0 = reinterpret_cast<const float4*>(b_att)[0 * D4 + jp];
    float4 ba1 = reinterpret_cast<const float4*>(b_att)[1 * D4 + jp];
    float4 ba2 = reinterpret_cast<const float4*>(b_att)[2 * D4 + jp];
    float4 ba3 = reinterpret_cast<const float4*>(b_att)[3 * D4 + jp];

    if (t == 0) s_nz = 0;

    const uint32_t smem_t0 = (uint32_t)__cvta_generic_to_shared(&s_tile[0][0]);
    const uint32_t smem_t1 = (uint32_t)__cvta_generic_to_shared(&s_tile[1][0]);

    // ---- prologue: stream tiles for groups g0, g0+1 ----
    {
        int ga = g0 < n_groups ? g0 : n_groups - 1;
        int gb = g0 + 1 < n_groups ? g0 + 1 : n_groups - 1;
        const float4* sa = reinterpret_cast<const float4*>(x + (size_t)ga * TILE_FLOATS);
        const float4* sb = reinterpret_cast<const float4*>(x + (size_t)gb * TILE_FLOATS);
        for (int i4 = t; i4 < TILE_VEC4; i4 += NT) cp_async16(smem_t0 + i4 * 16, sa + i4);
        cp_commit();
        for (int i4 = t; i4 < TILE_VEC4; i4 += NT) cp_async16(smem_t1 + i4 * 16, sb + i4);
        cp_commit();
    }

    #pragma unroll
    for (int i = 0; i < G; ++i) {
        if (i < G - 1) asm volatile("cp.async.wait_group 1;");
        else           asm volatile("cp.async.wait_group 0;");
        __syncthreads();                         // tile[i&1] visible to all

        const float* __restrict__ tile = s_tile[i & 1];
        const bool live = (g0 + i) < n_groups;

        // ---- stage A: partial scores + nonzero check (covers all 4000 floats) ----
        bool flag = false;
        if (t < 150) {
            const float4 ty = *reinterpret_cast<const float4*>(tile + 4 * jp);
            flag = (ty.x != 0.f) | (ty.y != 0.f) | (ty.z != 0.f) | (ty.w != 0.f);
            #pragma unroll
            for (int k = 0; k < 7; ++k) {
                const int n = nr + 6 * k;
                if (n < NW) {
                    float4 w = *reinterpret_cast<const float4*>(tile + (n + 1) * D + 4 * jp);
                    flag |= (w.x != 0.f) | (w.y != 0.f) | (w.z != 0.f) | (w.w != 0.f);
                    float p, q, a0, a1, a2, a3;
                    p = fmaf(w.x, wa0.x, ba0.x); q = fmaf(C_ABS, fabsf(p), p); a0 = ty.x * q;
                    p = fmaf(w.y, wa0.y, ba0.y); q = fmaf(C_ABS, fabsf(p), p); a0 = fmaf(ty.y, q, a0);
                    p = fmaf(w.z, wa0.z, ba0.z); q = fmaf(C_ABS, fabsf(p), p); a0 = fmaf(ty.z, q, a0);
                    p = fmaf(w.w, wa0.w, ba0.w); q = fmaf(C_ABS, fabsf(p), p); a0 = fmaf(ty.w, q, a0);
                    p = fmaf(w.x, wa1.x, ba1.x); q = fmaf(C_ABS, fabsf(p), p); a1 = ty.x * q;
                    p = fmaf(w.y, wa1.y, ba1.y); q = fmaf(C_ABS, fabsf(p), p); a1 = fmaf(ty.y, q, a1);
                    p = fmaf(w.z, wa1.z, ba1.z); q = fmaf(C_ABS, fabsf(p), p); a1 = fmaf(ty.z, q, a1);
                    p = fmaf(w.w, wa1.w, ba1.w); q = fmaf(C_ABS, fabsf(p), p); a1 = fmaf(ty.w, q, a1);
                    p = fmaf(w.x, wa2.x, ba2.x); q = fmaf(C_ABS, fabsf(p), p); a2 = ty.x * q;
                    p = fmaf(w.y, wa2.y, ba2.y); q = fmaf(C_ABS, fabsf(p), p); a2 = fmaf(ty.y, q, a2);
                    p = fmaf(w.z, wa2.z, ba2.z); q = fmaf(C_ABS, fabsf(p), p); a2 = fmaf(ty.z, q, a2);
                    p = fmaf(w.w, wa2.w, ba2.w); q = fmaf(C_ABS, fabsf(p), p); a2 = fmaf(ty.w, q, a2);
                    p = fmaf(w.x, wa3.x, ba3.x); q = fmaf(C_ABS, fabsf(p), p); a3 = ty.x * q;
                    p = fmaf(w.y, wa3.y, ba3.y); q = fmaf(C_ABS, fabsf(p), p); a3 = fmaf(ty.y, q, a3);
                    p = fmaf(w.z, wa3.z, ba3.z); q = fmaf(C_ABS, fabsf(p), p); a3 = fmaf(ty.z, q, a3);
                    p = fmaf(w.w, wa3.w, ba3.w); q = fmaf(C_ABS, fabsf(p), p); a3 = fmaf(ty.w, q, a3);
                    s_part[n * D4 + jp] = make_float4(a0, a1, a2, a3);
                }
            }
        }
        unsigned any = __ballot_sync(0xffffffffu, flag);
        if ((t & 31) == 0 && any) atomicOr(&s_nz, 1);
        __syncthreads();

        // ---- stage B: score(h,n) = sum_j part[n][j][h] ----
        if (t < NUM_HEADS * NW) {
            const float* pf = (const float*)s_part;
            const float* row = pf + (t >> 2) * 100 + (t & 3);
            float s0 = 0.f, s1 = 0.f;
            #pragma unroll
            for (int j = 0; j < 24; j += 2) {
                s0 += row[4 * j];
                s1 += row[4 * (j + 1)];
            }
            s0 += row[4 * 24];
            ((float*)s_e4)[t] = __expf(C_SCL * (s0 + s1));
        }
        __syncthreads();

        // ---- phase 3: per-head denominators ----
        if (t < 4 * 32) {
            const int h = t >> 5, lane = t & 31;
            const float* ef = (const float*)s_e4;
            float v = (lane < NW) ? ef[lane * 4 + h] : 0.f;
            if (lane < NW - 32) v += ef[(lane + 32) * 4 + h];
            #pragma unroll
            for (int off = 16; off; off >>= 1)
                v += __shfl_down_sync(0xffffffffu, v, off);
            if (lane == 0) s_inv[h] = __fdividef(1.f, v);
        }
        __syncthreads();

        // ---- phase 4: 25-thread register tile, all heads ----
        if (t < D4 && live) {
            float4 o0 = make_float4(0.f, 0.f, 0.f, 0.f);
            float4 o1 = o0, o2 = o0, o3 = o0;
            #pragma unroll 13
            for (int n = 0; n < NW; ++n) {
                float4 w = *reinterpret_cast<const float4*>(tile + (n + 1) * D + 4 * t);
                float4 e = s_e4[n];
                o0.x = fmaf(e.x, w.x, o0.x); o0.y = fmaf(e.x, w.y, o0.y);
                o0.z = fmaf(e.x, w.z, o0.z); o0.w = fmaf(e.x, w.w, o0.w);
                o1.x = fmaf(e.y, w.x, o1.x); o1.y = fmaf(e.y, w.y, o1.y);
                o1.z = fmaf(e.y, w.z, o1.z); o1.w = fmaf(e.y, w.w, o1.w);
                o2.x = fmaf(e.z, w.x, o2.x); o2.y = fmaf(e.z, w.y, o2.y);
                o2.z = fmaf(e.z, w.z, o2.z); o2.w = fmaf(e.z, w.w, o2.w);
                o3.x = fmaf(e.w, w.x, o3.x); o3.y = fmaf(e.w, w.y, o3.y);
                o3.z = fmaf(e.w, w.z, o3.z); o3.w = fmaf(e.w, w.w, o3.w);
            }
            float4* __restrict__ go4 =
                reinterpret_cast<float4*>(out + (size_t)(g0 + i) * (NUM_HEADS * D));
            const float4 zero = make_float4(0.f, 0.f, 0.f, 0.f);
            if (s_nz) {
                float i0 = s_inv[0], i1 = s_inv[1], i2 = s_inv[2], i3 = s_inv[3];
                go4[0 * D4 + t] = make_float4(o0.x * i0, o0.y * i0, o0.z * i0, o0.w * i0);
                go4[1 * D4 + t] = make_float4(o1.x * i1, o1.y * i1, o1.z * i1, o1.w * i1);
                go4[2 * D4 + t] = make_float4(o2.x * i2, o2.y * i2, o2.z * i2, o2.w * i2);
                go4[3 * D4 + t] = make_float4(o3.x * i3, o3.y * i3, o3.z * i3, o3.w * i3);
            } else {
                go4[0 * D4 + t] = zero; go4[1 * D4 + t] = zero;
                go4[2 * D4 + t] = zero; go4[3 * D4 + t] = zero;
            }
        }
        __syncthreads();                          // everyone done with tile[i&1] & s_nz
        if (t == 0) s_nz = 0;

        // ---- stream tile for group i+2 into the buffer just freed ----
        if (i + 2 < G) {
            int gn = g0 + i + 2 < n_groups ? g0 + i + 2 : n_groups - 1;
            const float4* sn = reinterpret_cast<const float4*>(x + (size_t)gn * TILE_FLOATS);
            const uint32_t dst = (i & 1) ? smem_t1 : smem_t0;
            for (int i4 = t; i4 < TILE_VEC4; i4 += NT) cp_async16(dst + i4 * 16, sn + i4);
            cp_commit();
        }
    }
}

extern "C" void kernel_launch(void* const* d_in, const int* in_sizes, int n_in,
                              void* d_out, int out_size)
{
    const float* x     = (const float*)d_in[0];
    const float* w_att = (const float*)d_in[1];
    const float* b_att = (const float*)d_in[2];
    float* out = (float*)d_out;

    int n_groups = in_sizes[0] / TILE_FLOATS;        // 4800
    int n_blocks = (n_groups + G - 1) / G;           // 1200
    tse_kernel<<<n_blocks, NT>>>(x, w_att, b_att, out, n_groups);
}